// round 2
// baseline (speedup 1.0000x reference)
#include <cuda_runtime.h>
#include <cstdint>

// Problem constants (fixed shapes)
#define B_ROWS   131072
#define IN_DIM   128
#define OUT_DIM  32
#define NBASIS   8
#define NFEAT    9            // 1 silu + 8 basis
#define KDIM     (IN_DIM * NFEAT)   // 1152

// Folded weight matrix W[K=1152][32] and bias[32]
__device__ __align__(16) float g_W[KDIM * OUT_DIM];
__device__ __align__(16) float g_bias[OUT_DIM];

// ---------------- packed f32x2 helpers (sm_103a) ----------------
__device__ __forceinline__ unsigned long long pk2(float v) {
    unsigned long long r;
    asm("mov.b64 %0, {%1, %1};" : "=l"(r) : "f"(v));
    return r;
}
__device__ __forceinline__ unsigned long long fma2(unsigned long long a,
                                                   unsigned long long b,
                                                   unsigned long long c) {
    unsigned long long d;
    asm("fma.rn.f32x2 %0, %1, %2, %3;" : "=l"(d) : "l"(a), "l"(b), "l"(c));
    return d;
}
__device__ __forceinline__ unsigned long long add2(unsigned long long a,
                                                   unsigned long long b) {
    unsigned long long d;
    asm("add.rn.f32x2 %0, %1, %2;" : "=l"(d) : "l"(a), "l"(b));
    return d;
}

// ---------------- spline constants ----------------
// grid = linspace(-1, 1, 12); centers = grid[3..10]; spacing = 2/5 + 1e-6
#define KAN_C0     (-1.0f + 6.0f / 11.0f)       // first center = -5/11
#define KAN_DSTEP  (2.0f / 11.0f)               // knot step
#define KAN_SPACE  (0.4f + 1e-6f)
#define KAN_INVS   (1.0f / KAN_SPACE)

// features: f[0] = silu(x), f[1..8] = exp(-0.5*((x-c_k)/s)^2)
__device__ __forceinline__ void kan_feats(float x, float f[NFEAT]) {
    float e = __expf(-x);
    f[0] = __fdividef(x, 1.0f + e);
    float z = (x - KAN_C0) * KAN_INVS;
    const float zs = KAN_DSTEP * KAN_INVS;
#pragma unroll
    for (int k = 0; k < NBASIS; ++k) {
        f[1 + k] = __expf(-0.5f * z * z);
        z -= zs;
    }
}

// ---------------- weight folding ----------------
// W[(i*9+0)][j]   = ew[i][j] * base_weight[i][j]
// W[(i*9+1+k)][j] = ew[i][j] * coeff[i][j][k]
__global__ void kan_prep(const float* __restrict__ coeff,
                         const float* __restrict__ bw,
                         const float* __restrict__ ew) {
    int t = blockIdx.x * blockDim.x + threadIdx.x;
    if (t >= IN_DIM * OUT_DIM) return;
    int i = t >> 5;          // input index
    int j = t & 31;          // output index
    float e = ew[t];
    g_W[(i * NFEAT) * OUT_DIM + j] = e * bw[t];
#pragma unroll
    for (int k = 0; k < NBASIS; ++k)
        g_W[(i * NFEAT + 1 + k) * OUT_DIM + j] = e * coeff[t * NBASIS + k];
}

__global__ void kan_prep_bias(const float* __restrict__ bb,
                              const float* __restrict__ ew) {
    int j = threadIdx.x;
    if (j < OUT_DIM) {
        float s = 0.0f;
        for (int i = 0; i < IN_DIM; ++i)
            s += ew[i * OUT_DIM + j] * bb[i * OUT_DIM + j];
        g_bias[j] = s;
    }
}

// ---------------- main kernel ----------------
// 64 threads/block, 2 rows/thread -> 128 rows/block, grid = 1024 blocks.
// Each thread: 32 output accumulators as 16 packed f32x2.
#define TPB        64
#define ROWS_BLK   128
#define CHUNK      16

__global__ __launch_bounds__(TPB)
void kan_main(const float* __restrict__ x, float* __restrict__ out) {
    __shared__ float xs[ROWS_BLK][CHUNK + 1];   // +1 pad: conflict-free column reads

    const int tid = threadIdx.x;
    const long long base = (long long)blockIdx.x * ROWS_BLK;
    const float* __restrict__ xblk = x + base * IN_DIM;

    unsigned long long acc0[16], acc1[16];
#pragma unroll
    for (int h = 0; h < 16; ++h) { acc0[h] = 0ull; acc1[h] = 0ull; }

    for (int i0 = 0; i0 < IN_DIM; i0 += CHUNK) {
        __syncthreads();
        // stage x[128 rows][16 cols] (coalesced 64B-contiguous per row)
#pragma unroll
        for (int k = 0; k < (ROWS_BLK * CHUNK) / TPB; ++k) {
            int e = tid + k * TPB;
            int r = e >> 4, c = e & 15;
            xs[r][c] = xblk[r * IN_DIM + i0 + c];
        }
        __syncthreads();

#pragma unroll 1
        for (int ii = 0; ii < CHUNK; ++ii) {
            const int i = i0 + ii;
            float fa[NFEAT], fb[NFEAT];
            kan_feats(xs[tid][ii], fa);
            kan_feats(xs[tid + TPB][ii], fb);

            const ulonglong2* __restrict__ wp =
                (const ulonglong2*)(g_W + i * (NFEAT * OUT_DIM));
#pragma unroll
            for (int f = 0; f < NFEAT; ++f) {
                unsigned long long pa = pk2(fa[f]);
                unsigned long long pb = pk2(fb[f]);
#pragma unroll
                for (int h = 0; h < 8; ++h) {
                    ulonglong2 w = wp[f * 8 + h];       // W[i*9+f][4h .. 4h+3]
                    acc0[2 * h]     = fma2(pa, w.x, acc0[2 * h]);
                    acc0[2 * h + 1] = fma2(pa, w.y, acc0[2 * h + 1]);
                    acc1[2 * h]     = fma2(pb, w.x, acc1[2 * h]);
                    acc1[2 * h + 1] = fma2(pb, w.y, acc1[2 * h + 1]);
                }
            }
        }
    }

    // add bias, store 32 floats per row as 8x STG.128
    const unsigned long long* bp = (const unsigned long long*)g_bias;
    ulonglong2* o0 = (ulonglong2*)(out + (base + tid) * OUT_DIM);
    ulonglong2* o1 = (ulonglong2*)(out + (base + TPB + tid) * OUT_DIM);
#pragma unroll
    for (int h = 0; h < 8; ++h) {
        unsigned long long b0 = bp[2 * h], b1 = bp[2 * h + 1];
        ulonglong2 v0, v1;
        v0.x = add2(acc0[2 * h], b0);
        v0.y = add2(acc0[2 * h + 1], b1);
        v1.x = add2(acc1[2 * h], b0);
        v1.y = add2(acc1[2 * h + 1], b1);
        o0[h] = v0;
        o1[h] = v1;
    }
}

// ---------------- launch ----------------
extern "C" void kernel_launch(void* const* d_in, const int* in_sizes, int n_in,
                              void* d_out, int out_size) {
    (void)in_sizes; (void)n_in; (void)out_size;
    const float* x     = (const float*)d_in[0];
    const float* coeff = (const float*)d_in[1];
    const float* bw    = (const float*)d_in[2];
    const float* bb    = (const float*)d_in[3];
    const float* ew    = (const float*)d_in[4];
    float* out = (float*)d_out;

    kan_prep<<<(IN_DIM * OUT_DIM + 255) / 256, 256>>>(coeff, bw, ew);
    kan_prep_bias<<<1, 32>>>(bb, ew);
    kan_main<<<B_ROWS / ROWS_BLK, TPB>>>(x, out);
}